// round 2
// baseline (speedup 1.0000x reference)
#include <cuda_runtime.h>
#include <math.h>

#define HID 128
#define NHEAD 4
#define CDIM 128
#define HC 512          // NHEAD * CDIM
#define NLAYER 3
#define NMAX 10240
#define BMAX 64

// ---------------- device scratch (static, no allocation) ----------------
static __device__ float g_h   [(size_t)NMAX * HID];   // node features (residual stream)
static __device__ float g_hw  [(size_t)NMAX * HC];    // h @ W  -> [N, H, C]
static __device__ float g_asrc[NMAX * NHEAD];
static __device__ float g_adst[NMAX * NHEAD];
static __device__ float g_max [NMAX * NHEAD];
static __device__ float g_sum [NMAX * NHEAD];
static __device__ float g_out [(size_t)NMAX * HID];   // aggregated (head-mean) output
static __device__ float g_pool[BMAX * HID];
static __device__ float g_cnt [BMAX];
static __device__ int   g_is64;                       // 1 if indices are int64, 0 if int32

// ---------------- helpers ----------------
__device__ __forceinline__ float lrelu(float x) { return x > 0.f ? x : 0.2f * x; }

__device__ __forceinline__ void atomicMaxF(float* a, float v) {
    if (v >= 0.f) atomicMax((int*)a, __float_as_int(v));
    else          atomicMin((unsigned int*)a, __float_as_uint(v));
}

__device__ __forceinline__ void redAdd4(float* p, float4 v) {
    asm volatile("red.global.add.v4.f32 [%0], {%1,%2,%3,%4};"
                 :: "l"(p), "f"(v.x), "f"(v.y), "f"(v.z), "f"(v.w) : "memory");
}

__device__ __forceinline__ int idx_at(const void* p, int i, int is64) {
    return is64 ? (int)((const long long*)p)[i] : ((const int*)p)[i];
}

// detect whether index tensors are int64 or int32 (jax usually demotes to int32)
__global__ void k_detect(const void* ei, int M) {
    const long long* p = (const long long*)ei;
    int ok = 1;
    for (int i = 0; i < 16; i++) {
        long long v = p[i];
        if (v < 0 || v >= (long long)M) { ok = 0; break; }
    }
    g_is64 = ok;
}

// ---------------- kernels ----------------

// h0 = relu(x @ node_W + node_b), x:[N,5], node_W:[5,128]
__global__ void k_init(const float* __restrict__ x, const float* __restrict__ W,
                       const float* __restrict__ b, int M) {
    int i = blockIdx.x * blockDim.x + threadIdx.x;
    if (i >= M * HID) return;
    int n = i >> 7, j = i & 127;
    float acc = b[j];
#pragma unroll
    for (int k = 0; k < 5; k++) acc += x[n * 5 + k] * W[k * HID + j];
    g_h[i] = fmaxf(acc, 0.f);
}

// g_hw = g_h @ W   (M x 128) @ (128 x 512), tiled fp32
__global__ void k_gemm(const float* __restrict__ W, int M) {
    __shared__ float As[32][68];   // transposed A tile: As[k][m]
    __shared__ float Bs[32][68];   // Bs[k][n]
    int bn = blockIdx.x * 64;
    int bm = blockIdx.y * 64;
    int tid = threadIdx.x;                 // 256 threads
    int tx = tid & 15, ty = tid >> 4;
    float acc[4][4] = {};
    for (int k0 = 0; k0 < 128; k0 += 32) {
#pragma unroll
        for (int i = 0; i < 2; i++) {
            int idx = tid + i * 256;       // 0..511
            int r   = idx >> 3;            // row in tile (0..63)
            int kk  = (idx & 7) << 2;      // k offset (0..28)
            int grow = bm + r;
            float4 v = make_float4(0.f, 0.f, 0.f, 0.f);
            if (grow < M) v = *(const float4*)(g_h + (size_t)grow * HID + k0 + kk);
            As[kk + 0][r] = v.x; As[kk + 1][r] = v.y;
            As[kk + 2][r] = v.z; As[kk + 3][r] = v.w;
        }
#pragma unroll
        for (int i = 0; i < 2; i++) {
            int idx = tid + i * 256;
            int r   = idx >> 4;            // k row (0..31)
            int cc  = (idx & 15) << 2;     // col offset (0..60)
            *(float4*)&Bs[r][cc] = *(const float4*)(W + (size_t)(k0 + r) * HC + bn + cc);
        }
        __syncthreads();
#pragma unroll
        for (int k = 0; k < 32; k++) {
            float4 a = *(float4*)&As[k][ty << 2];
            float4 b = *(float4*)&Bs[k][tx << 2];
            acc[0][0] += a.x * b.x; acc[0][1] += a.x * b.y; acc[0][2] += a.x * b.z; acc[0][3] += a.x * b.w;
            acc[1][0] += a.y * b.x; acc[1][1] += a.y * b.y; acc[1][2] += a.y * b.z; acc[1][3] += a.y * b.w;
            acc[2][0] += a.z * b.x; acc[2][1] += a.z * b.y; acc[2][2] += a.z * b.z; acc[2][3] += a.z * b.w;
            acc[3][0] += a.w * b.x; acc[3][1] += a.w * b.y; acc[3][2] += a.w * b.z; acc[3][3] += a.w * b.w;
        }
        __syncthreads();
    }
#pragma unroll
    for (int i = 0; i < 4; i++) {
        int grow = bm + (ty << 2) + i;
        if (grow < M) {
            float4 o = make_float4(acc[i][0], acc[i][1], acc[i][2], acc[i][3]);
            *(float4*)(g_hw + (size_t)grow * HC + bn + (tx << 2)) = o;
        }
    }
}

// a_src[n,h] = <hw[n,h,:], att_src[h,:]>, same for a_dst. Block=128 (warp per head).
__global__ void k_att(const float* __restrict__ att_src, const float* __restrict__ att_dst, int M) {
    int n = blockIdx.x;
    if (n >= M) return;
    int t = threadIdx.x, w = t >> 5, lane = t & 31;
    const float4* hv = (const float4*)(g_hw + (size_t)n * HC + w * CDIM);
    const float4* s4 = (const float4*)(att_src + w * CDIM);
    const float4* d4 = (const float4*)(att_dst + w * CDIM);
    float4 h4 = hv[lane], a = s4[lane], b = d4[lane];
    float ss = h4.x * a.x + h4.y * a.y + h4.z * a.z + h4.w * a.w;
    float sd = h4.x * b.x + h4.y * b.y + h4.z * b.z + h4.w * b.w;
#pragma unroll
    for (int o = 16; o; o >>= 1) {
        ss += __shfl_xor_sync(~0u, ss, o);
        sd += __shfl_xor_sync(~0u, sd, o);
    }
    if (!lane) { g_asrc[n * 4 + w] = ss; g_adst[n * 4 + w] = sd; }
}

__global__ void k_reset(int M) {
    int i = blockIdx.x * blockDim.x + threadIdx.x;
    if (i >= M * NHEAD) return;
    g_max[i] = -1e30f;
    g_sum[i] = 0.f;
}

__global__ void k_zero_out(int M) {
    int i = blockIdx.x * blockDim.x + threadIdx.x;
    if (i >= M * HID) return;
    g_out[i] = 0.f;
}

// pass A: segment max of e over dst. Threads cover E edges + M self-loops.
__global__ void k_edge_max(const void* __restrict__ ei, int E, int M) {
    int i = blockIdx.x * blockDim.x + threadIdx.x;
    if (i >= E + M) return;
    int is64 = g_is64;
    int s, d;
    if (i < E) { s = idx_at(ei, i, is64); d = idx_at(ei, E + i, is64); } else { s = d = i - E; }
    float4 as = *(const float4*)(g_asrc + s * 4);
    float4 ad = *(const float4*)(g_adst + d * 4);
    atomicMaxF(g_max + d * 4 + 0, lrelu(as.x + ad.x));
    atomicMaxF(g_max + d * 4 + 1, lrelu(as.y + ad.y));
    atomicMaxF(g_max + d * 4 + 2, lrelu(as.z + ad.z));
    atomicMaxF(g_max + d * 4 + 3, lrelu(as.w + ad.w));
}

// pass B: segment sum of exp(e - max)
__global__ void k_edge_sum(const void* __restrict__ ei, int E, int M) {
    int i = blockIdx.x * blockDim.x + threadIdx.x;
    if (i >= E + M) return;
    int is64 = g_is64;
    int s, d;
    if (i < E) { s = idx_at(ei, i, is64); d = idx_at(ei, E + i, is64); } else { s = d = i - E; }
    float4 as = *(const float4*)(g_asrc + s * 4);
    float4 ad = *(const float4*)(g_adst + d * 4);
    float4 m  = *(const float4*)(g_max + d * 4);
    atomicAdd(g_sum + d * 4 + 0, expf(lrelu(as.x + ad.x) - m.x));
    atomicAdd(g_sum + d * 4 + 1, expf(lrelu(as.y + ad.y) - m.y));
    atomicAdd(g_sum + d * 4 + 2, expf(lrelu(as.z + ad.z) - m.z));
    atomicAdd(g_sum + d * 4 + 3, expf(lrelu(as.w + ad.w) - m.w));
}

// pass C: one warp per edge; accumulate head-mean of alpha*hw[src] into out[dst]
__global__ void k_edge_acc(const void* __restrict__ ei, int E, int M) {
    int gid = blockIdx.x * blockDim.x + threadIdx.x;
    int w = gid >> 5, lane = gid & 31;
    if (w >= E + M) return;
    int is64 = g_is64;
    int s, d;
    if (w < E) { s = idx_at(ei, w, is64); d = idx_at(ei, E + w, is64); } else { s = d = w - E; }
    float4 as = *(const float4*)(g_asrc + s * 4);
    float4 ad = *(const float4*)(g_adst + d * 4);
    float4 m  = *(const float4*)(g_max + d * 4);
    float4 sm = *(const float4*)(g_sum + d * 4);
    // alpha per head, pre-scaled by 1/NHEAD (head mean folded in)
    float a0 = expf(lrelu(as.x + ad.x) - m.x) / (sm.x + 1e-16f) * 0.25f;
    float a1 = expf(lrelu(as.y + ad.y) - m.y) / (sm.y + 1e-16f) * 0.25f;
    float a2 = expf(lrelu(as.z + ad.z) - m.z) / (sm.z + 1e-16f) * 0.25f;
    float a3 = expf(lrelu(as.w + ad.w) - m.w) / (sm.w + 1e-16f) * 0.25f;
    const float4* hs = (const float4*)(g_hw + (size_t)s * HC);
    float4 v0 = hs[lane];          // head 0, cols lane*4..+3
    float4 v1 = hs[32 + lane];     // head 1
    float4 v2 = hs[64 + lane];     // head 2
    float4 v3 = hs[96 + lane];     // head 3
    float4 r;
    r.x = a0 * v0.x + a1 * v1.x + a2 * v2.x + a3 * v3.x;
    r.y = a0 * v0.y + a1 * v1.y + a2 * v2.y + a3 * v3.y;
    r.z = a0 * v0.z + a1 * v1.z + a2 * v2.z + a3 * v3.z;
    r.w = a0 * v0.w + a1 * v1.w + a2 * v2.w + a3 * v3.w;
    redAdd4(g_out + (size_t)d * HID + lane * 4, r);
}

// bias + layernorm + relu + residual. Block = 128 threads per node.
__global__ void k_post(const float* __restrict__ bias, const float* __restrict__ lng,
                       const float* __restrict__ lnb, int M) {
    int n = blockIdx.x;
    if (n >= M) return;
    int t = threadIdx.x;
    float v = g_out[(size_t)n * HID + t] + bias[t];
    __shared__ float sh[4];
    float s = v;
#pragma unroll
    for (int o = 16; o; o >>= 1) s += __shfl_xor_sync(~0u, s, o);
    if ((t & 31) == 0) sh[t >> 5] = s;
    __syncthreads();
    float mu = (sh[0] + sh[1] + sh[2] + sh[3]) * (1.f / 128.f);
    __syncthreads();
    float dv = v - mu;
    float q = dv * dv;
#pragma unroll
    for (int o = 16; o; o >>= 1) q += __shfl_xor_sync(~0u, q, o);
    if ((t & 31) == 0) sh[t >> 5] = q;
    __syncthreads();
    float var = (sh[0] + sh[1] + sh[2] + sh[3]) * (1.f / 128.f);
    float ln = dv * rsqrtf(var + 1e-5f) * lng[t] + lnb[t];
    g_h[(size_t)n * HID + t] += fmaxf(ln, 0.f);
}

__global__ void k_pool_zero() {
    int i = blockIdx.x * blockDim.x + threadIdx.x;
    if (i < BMAX * HID) g_pool[i] = 0.f;
    if (i < BMAX) g_cnt[i] = 0.f;
}

// one warp per node: float4 red-add per lane into its graph's pool slot
__global__ void k_pool(const void* __restrict__ batch, int M) {
    int gid = blockIdx.x * blockDim.x + threadIdx.x;
    int n = gid >> 5, lane = gid & 31;
    if (n >= M) return;
    int b = idx_at(batch, n, g_is64);
    float4 v = *(const float4*)(g_h + (size_t)n * HID + lane * 4);
    redAdd4(g_pool + b * HID + lane * 4, v);
    if (lane == 0) atomicAdd(g_cnt + b, 1.f);
}

// final output: [h (M*128) | graph_emb]
__global__ void k_write(float* __restrict__ dout, int M, int total) {
    int i = blockIdx.x * blockDim.x + threadIdx.x;
    if (i >= total) return;
    int nh = M * HID;
    if (i < nh) {
        dout[i] = g_h[i];
    } else {
        int j = i - nh;
        dout[i] = g_pool[j] / fmaxf(g_cnt[j >> 7], 1.f);
    }
}

// ---------------- launch ----------------
extern "C" void kernel_launch(void* const* d_in, const int* in_sizes, int n_in,
                              void* d_out, int out_size) {
    const float* x        = (const float*)d_in[0];
    const void*  ei       = d_in[1];
    const void*  batch    = d_in[2];
    const float* node_W   = (const float*)d_in[3];
    const float* node_b   = (const float*)d_in[4];
    const float* Ws       = (const float*)d_in[5];
    const float* att_srcs = (const float*)d_in[6];
    const float* att_dsts = (const float*)d_in[7];
    const float* biases   = (const float*)d_in[8];
    const float* ln_gs    = (const float*)d_in[9];
    const float* ln_bs    = (const float*)d_in[10];

    int M = in_sizes[2];          // N nodes
    int E = in_sizes[1] / 2;      // edges (before self-loops)
    int EM = E + M;
    float* dout = (float*)d_out;

    k_detect<<<1, 1>>>(ei, M);
    k_init<<<(M * HID + 255) / 256, 256>>>(x, node_W, node_b, M);

    for (int l = 0; l < NLAYER; l++) {
        k_gemm<<<dim3(8, (M + 63) / 64), 256>>>(Ws + (size_t)l * HID * HC, M);
        k_att<<<M, 128>>>(att_srcs + l * HC, att_dsts + l * HC, M);
        k_reset<<<(M * NHEAD + 255) / 256, 256>>>(M);
        k_zero_out<<<(M * HID + 255) / 256, 256>>>(M);
        k_edge_max<<<(EM + 255) / 256, 256>>>(ei, E, M);
        k_edge_sum<<<(EM + 255) / 256, 256>>>(ei, E, M);
        k_edge_acc<<<((size_t)EM * 32 + 255) / 256, 256>>>(ei, E, M);
        k_post<<<M, 128>>>(biases + l * HID, ln_gs + l * HID, ln_bs + l * HID, M);
    }

    k_pool_zero<<<(BMAX * HID + 255) / 256, 256>>>();
    k_pool<<<((size_t)M * 32 + 255) / 256, 256>>>(batch, M);
    k_write<<<(out_size + 255) / 256, 256>>>(dout, M, out_size);
}